// round 15
// baseline (speedup 1.0000x reference)
#include <cuda_runtime.h>
#include <cuda_fp16.h>
#include <math.h>
#include <stdint.h>

// Problem constants
#define BATCH   2
#define SEQ     2048
#define CDIM    2048
#define NHEAD   16
#define NKV     4
#define HDIM    128
#define MROWS   (BATCH * SEQ)          // 4096
#define KVDIM   (NKV * HDIM)           // 512
#define SCALE   0.08838834764831845f   // 1/sqrt(128)

// Projection GEMM tiling
#define BM 128
#define BN 128
#define BK 32
#define RS 20                          // words per smem row (16 data + 4 pad)
#define PLANE_W (128 * RS)
#define PLANE_B (PLANE_W * 4)          // 10240 B
#define SMEM_PROJ (2 * 4 * PLANE_B)    // 81920 B (double-buffered 4 planes)
#define NTHREADS 256

// Flash kernel smem: 6 planes of [128 rows x 68 words]
#define FW  68
#define FPL (128 * FW)
#define SMEM_FLASH (6 * FPL * 4)       // 208896 B

// ---------------------------------------------------------------------------
// Static device scratch
// ---------------------------------------------------------------------------
__device__ float  g_q[(size_t)MROWS * CDIM];             // fp32 q (pre-rope)
__device__ float  g_k[(size_t)MROWS * KVDIM];
__device__ float  g_v[(size_t)MROWS * KVDIM];
// pre-split fp16 hi/lo planes
__device__ __half g_xh[(size_t)MROWS * CDIM],  g_xl[(size_t)MROWS * CDIM];
__device__ __half g_wqh[(size_t)CDIM * CDIM],  g_wql[(size_t)CDIM * CDIM];
__device__ __half g_wkh[(size_t)KVDIM * CDIM], g_wkl[(size_t)KVDIM * CDIM];
__device__ __half g_wvh[(size_t)KVDIM * CDIM], g_wvl[(size_t)KVDIM * CDIM];
__device__ __half g_woh[(size_t)CDIM * CDIM],  g_wol[(size_t)CDIM * CDIM];
__device__ __half g_qh[(size_t)MROWS * CDIM],  g_ql[(size_t)MROWS * CDIM];
__device__ __half g_kh[(size_t)MROWS * KVDIM], g_kl[(size_t)MROWS * KVDIM];
__device__ __half g_vth[(size_t)BATCH * KVDIM * SEQ], g_vtl[(size_t)BATCH * KVDIM * SEQ];
__device__ __half g_ah[(size_t)MROWS * CDIM],  g_al[(size_t)MROWS * CDIM]; // attn out split

// ---------------------------------------------------------------------------
// Helpers
// ---------------------------------------------------------------------------
__device__ __forceinline__ uint32_t s2u(const void* p) {
    uint32_t a;
    asm("{ .reg .u64 t; cvta.to.shared.u64 t, %1; cvt.u32.u64 %0, t; }" : "=r"(a) : "l"(p));
    return a;
}
__device__ __forceinline__ void split2(float x, float y, uint32_t& hw, uint32_t& lw) {
    __half2 h = __floats2half2_rn(x, y);
    float2 hf = __half22float2(h);
    __half2 l = __floats2half2_rn(x - hf.x, y - hf.y);
    hw = *reinterpret_cast<uint32_t*>(&h);
    lw = *reinterpret_cast<uint32_t*>(&l);
}
__device__ __forceinline__ void ldsm4(uint32_t addr, uint32_t& r0, uint32_t& r1,
                                      uint32_t& r2, uint32_t& r3) {
    asm volatile("ldmatrix.sync.aligned.m8n8.x4.shared.b16 {%0,%1,%2,%3}, [%4];"
                 : "=r"(r0), "=r"(r1), "=r"(r2), "=r"(r3) : "r"(addr));
}
__device__ __forceinline__ void mma16(float* d, uint32_t a0, uint32_t a1, uint32_t a2,
                                      uint32_t a3, uint32_t b0, uint32_t b1) {
    asm volatile(
        "mma.sync.aligned.m16n8k16.row.col.f32.f16.f16.f32 "
        "{%0,%1,%2,%3}, {%4,%5,%6,%7}, {%8,%9}, {%0,%1,%2,%3};"
        : "+f"(d[0]), "+f"(d[1]), "+f"(d[2]), "+f"(d[3])
        : "r"(a0), "r"(a1), "r"(a2), "r"(a3), "r"(b0), "r"(b1));
}
__device__ __forceinline__ void cp16(uint32_t dst, const void* src) {
    asm volatile("cp.async.cg.shared.global [%0], [%1], 16;" :: "r"(dst), "l"(src));
}
#define CP_COMMIT() asm volatile("cp.async.commit_group;" ::: "memory")
#define CP_WAIT0()  asm volatile("cp.async.wait_group 0;" ::: "memory")
#define CP_WAIT1()  asm volatile("cp.async.wait_group 1;" ::: "memory")

// ---------------------------------------------------------------------------
// Elementwise fp16 hi/lo split
// ---------------------------------------------------------------------------
__global__ __launch_bounds__(256) void k_split(const float4* __restrict__ src,
                                               uint2* __restrict__ h,
                                               uint2* __restrict__ l, int n4) {
    int i = blockIdx.x * 256 + threadIdx.x;
    if (i >= n4) return;
    float4 v = src[i];
    uint32_t h0, l0, h1, l1;
    split2(v.x, v.y, h0, l0);
    split2(v.z, v.w, h1, l1);
    h[i] = make_uint2(h0, h1);
    l[i] = make_uint2(l0, l1);
}

// ---------------------------------------------------------------------------
// NT GEMM core on pre-split fp16 planes, cp.async double-buffered staging.
// MMA order is term-major per mt (chain distance 4) to hide HMMA latency.
// ---------------------------------------------------------------------------
__device__ void gemm_async_nt(const __half* __restrict__ Ah, const __half* __restrict__ Al,
                              int lda,
                              const __half* __restrict__ Bh, const __half* __restrict__ Bl,
                              int ldb,
                              float* __restrict__ C, int ldc,
                              int K, int bxn, int bym)
{
    extern __shared__ uint32_t psm[];
    const uint32_t ub = s2u(psm);

    const int tid  = threadIdx.x;
    const int lane = tid & 31;
    const int warp = tid >> 5;
    const int gid  = lane >> 2;
    const int tig  = lane & 3;
    const int wm   = (warp & 1) * 64;
    const int wn   = (warp >> 1) * 32;

    const int r  = tid >> 1;
    const int hf = tid & 1;
    const __half* pAh = Ah + (size_t)(bym * BM + r) * lda + hf * 16;
    const __half* pAl = Al + (size_t)(bym * BM + r) * lda + hf * 16;
    const __half* pBh = Bh + (size_t)(bxn * BN + r) * ldb + hf * 16;
    const __half* pBl = Bl + (size_t)(bxn * BN + r) * ldb + hf * 16;
    const uint32_t dst0 = ub + (uint32_t)(r * RS + hf * 8) * 4u;

    float acc[4][4][4];
#pragma unroll
    for (int i = 0; i < 4; i++)
#pragma unroll
        for (int j = 0; j < 4; j++)
#pragma unroll
            for (int q = 0; q < 4; q++) acc[i][j][q] = 0.0f;

    const int NCC = K / BK;

    {
        cp16(dst0,                 pAh);
        cp16(dst0 + 16,            pAh + 8);
        cp16(dst0 + PLANE_B,       pAl);
        cp16(dst0 + PLANE_B + 16,  pAl + 8);
        cp16(dst0 + 2 * PLANE_B,      pBh);
        cp16(dst0 + 2 * PLANE_B + 16, pBh + 8);
        cp16(dst0 + 3 * PLANE_B,      pBl);
        cp16(dst0 + 3 * PLANE_B + 16, pBl + 8);
        CP_COMMIT();
    }

    for (int kc = 0; kc < NCC; kc++) {
        if (kc + 1 < NCC) {
            const uint32_t d = dst0 + (uint32_t)(((kc + 1) & 1) * 4 * PLANE_B);
            const int ko = (kc + 1) * BK;
            cp16(d,                 pAh + ko);
            cp16(d + 16,            pAh + ko + 8);
            cp16(d + PLANE_B,       pAl + ko);
            cp16(d + PLANE_B + 16,  pAl + ko + 8);
            cp16(d + 2 * PLANE_B,      pBh + ko);
            cp16(d + 2 * PLANE_B + 16, pBh + ko + 8);
            cp16(d + 3 * PLANE_B,      pBl + ko);
            cp16(d + 3 * PLANE_B + 16, pBl + ko + 8);
            CP_COMMIT();
            CP_WAIT1();
        } else {
            CP_WAIT0();
        }
        __syncthreads();

        const int bufw = (kc & 1) * 4 * PLANE_W;
        const uint32_t bufb = (uint32_t)(kc & 1) * 4u * PLANE_B;
        const uint32_t* sBh = psm + bufw + 2 * PLANE_W;
        const uint32_t* sBl = psm + bufw + 3 * PLANE_W;

#pragma unroll
        for (int ks = 0; ks < 2; ks++) {
            const int kw = ks * 8;
            uint32_t bh[4][2], bl[4][2];
#pragma unroll
            for (int nt = 0; nt < 4; nt++) {
                const int bidx = (wn + nt * 8 + gid) * RS + kw + tig;
                bh[nt][0] = sBh[bidx];
                bh[nt][1] = sBh[bidx + 4];
                bl[nt][0] = sBl[bidx];
                bl[nt][1] = sBl[bidx + 4];
            }
#pragma unroll
            for (int mt = 0; mt < 4; mt++) {
                const int arow = wm + mt * 16 + (lane & 15);
                const uint32_t aoff = bufb + (uint32_t)(arow * RS + kw + (lane >> 4) * 4) * 4u;
                uint32_t ah0, ah1, ah2, ah3, al0, al1, al2, al3;
                ldsm4(ub + aoff,           ah0, ah1, ah2, ah3);
                ldsm4(ub + PLANE_B + aoff, al0, al1, al2, al3);
                // term-major: consecutive MMAs hit different accumulators
#pragma unroll
                for (int nt = 0; nt < 4; nt++)
                    mma16(acc[mt][nt], ah0, ah1, ah2, ah3, bh[nt][0], bh[nt][1]);
#pragma unroll
                for (int nt = 0; nt < 4; nt++)
                    mma16(acc[mt][nt], ah0, ah1, ah2, ah3, bl[nt][0], bl[nt][1]);
#pragma unroll
                for (int nt = 0; nt < 4; nt++)
                    mma16(acc[mt][nt], al0, al1, al2, al3, bh[nt][0], bh[nt][1]);
            }
        }
        __syncthreads();
    }

    float* Cb = C + (size_t)bym * BM * ldc + (size_t)bxn * BN;
#pragma unroll
    for (int mt = 0; mt < 4; mt++) {
        const int row = wm + mt * 16 + gid;
#pragma unroll
        for (int nt = 0; nt < 4; nt++) {
            const int col = wn + nt * 8 + 2 * tig;
            *reinterpret_cast<float2*>(Cb + (size_t)row * ldc + col) =
                make_float2(acc[mt][nt][0], acc[mt][nt][1]);
            *reinterpret_cast<float2*>(Cb + (size_t)(row + 8) * ldc + col) =
                make_float2(acc[mt][nt][2], acc[mt][nt][3]);
        }
    }
}

// Fused Q/K/V projections: grid.x = 24 (16 Q, 4 K, 4 V n-blocks). 2 CTAs/SM.
__global__ __launch_bounds__(NTHREADS, 2) void k_qkv() {
    const int bx = blockIdx.x;
    const __half *Bh, *Bl;
    float* O;
    int ldo, nb;
    if (bx < 16)      { Bh = g_wqh; Bl = g_wql; O = g_q; ldo = CDIM;  nb = bx; }
    else if (bx < 20) { Bh = g_wkh; Bl = g_wkl; O = g_k; ldo = KVDIM; nb = bx - 16; }
    else              { Bh = g_wvh; Bl = g_wvl; O = g_v; ldo = KVDIM; nb = bx - 20; }
    gemm_async_nt(g_xh, g_xl, CDIM, Bh, Bl, CDIM, O, ldo, CDIM, nb, blockIdx.y);
}
__global__ __launch_bounds__(NTHREADS, 2) void k_oproj(float* __restrict__ out) {
    gemm_async_nt(g_ah, g_al, CDIM, g_woh, g_wol, CDIM, out, CDIM, CDIM,
                  blockIdx.x, blockIdx.y);
}

// ---------------------------------------------------------------------------
// RoPE + fp16 pre-split (scaled q, k)
// ---------------------------------------------------------------------------
__global__ void k_rope_split(const int* __restrict__ start_pos) {
    __shared__ float cs[HDIM / 2], sn[HDIM / 2];
    const int bt  = blockIdx.x;
    const int t   = bt & (SEQ - 1);
    const int tid = threadIdx.x;

    if (tid < HDIM / 2) {
        double inv = pow(10000.0, -(double)(2 * tid) / (double)HDIM);
        double ang = (double)(t + start_pos[0]) * inv;
        cs[tid] = (float)cos(ang);
        sn[tid] = (float)sin(ang);
    }
    __syncthreads();

    const float* qrow = g_q + (size_t)bt * CDIM;
    __half* qh = g_qh + (size_t)bt * CDIM;
    __half* ql = g_ql + (size_t)bt * CDIM;
    for (int idx = tid; idx < NHEAD * (HDIM / 2); idx += blockDim.x) {
        int h = idx >> 6, i = idx & 63;
        float x1 = qrow[h * HDIM + i];
        float x2 = qrow[h * HDIM + i + 64];
        float r1 = (x1 * cs[i] - x2 * sn[i]) * SCALE;
        float r2 = (x2 * cs[i] + x1 * sn[i]) * SCALE;
        __half h1 = __float2half_rn(r1);
        __half h2 = __float2half_rn(r2);
        qh[h * HDIM + i]      = h1;
        ql[h * HDIM + i]      = __float2half_rn(r1 - __half2float(h1));
        qh[h * HDIM + i + 64] = h2;
        ql[h * HDIM + i + 64] = __float2half_rn(r2 - __half2float(h2));
    }

    const float* krow = g_k + (size_t)bt * KVDIM;
    __half* kh = g_kh + (size_t)bt * KVDIM;
    __half* kl = g_kl + (size_t)bt * KVDIM;
    for (int idx = tid; idx < NKV * (HDIM / 2); idx += blockDim.x) {
        int h = idx >> 6, i = idx & 63;
        float x1 = krow[h * HDIM + i];
        float x2 = krow[h * HDIM + i + 64];
        float r1 = x1 * cs[i] - x2 * sn[i];
        float r2 = x2 * cs[i] + x1 * sn[i];
        __half h1 = __float2half_rn(r1);
        __half h2 = __float2half_rn(r2);
        kh[h * HDIM + i]      = h1;
        kl[h * HDIM + i]      = __float2half_rn(r1 - __half2float(h1));
        kh[h * HDIM + i + 64] = h2;
        kl[h * HDIM + i + 64] = __float2half_rn(r2 - __half2float(h2));
    }
}

// ---------------------------------------------------------------------------
// V transpose + split
// ---------------------------------------------------------------------------
__global__ void k_vt2() {
    __shared__ float tile[32][33];
    const int b  = blockIdx.z;
    const int t0 = blockIdx.x * 32;
    const int d0 = blockIdx.y * 32;
    const int tx = threadIdx.x, ty = threadIdx.y;
#pragma unroll
    for (int j = 0; j < 4; j++) {
        tile[ty + 8 * j][tx] =
            g_v[((size_t)b * SEQ + t0 + ty + 8 * j) * KVDIM + d0 + tx];
    }
    __syncthreads();
#pragma unroll
    for (int j = 0; j < 4; j++) {
        float v = tile[tx][ty + 8 * j];
        __half hh = __float2half_rn(v);
        size_t o = ((size_t)b * KVDIM + d0 + ty + 8 * j) * SEQ + t0 + tx;
        g_vth[o] = hh;
        g_vtl[o] = __float2half_rn(v - __half2float(hh));
    }
}

// ---------------------------------------------------------------------------
// Fused flash attention: pipelined cp.async staging; non-trans ldmatrix B
// fragments; split-term MMAs interleaved across the two n-tiles of each j
// (dependency distance 2) to hide HMMA latency at 2 warps/SMSP.
// grid (SEQ/128, BATCH*NHEAD), 256 threads, 1 CTA/SM.
// ---------------------------------------------------------------------------
__global__ __launch_bounds__(256, 1) void k_flash() {
    extern __shared__ uint32_t fsm[];
    const uint32_t ub = s2u(fsm);

    const int tid  = threadIdx.x;
    const int lane = tid & 31;
    const int warp = tid >> 5;
    const int gid  = lane >> 2;
    const int tig  = lane & 3;
    const int z = blockIdx.y, b = z >> 4, h = z & 15, g = h >> 2;

    const int r  = tid >> 1;
    const int ch = tid & 1;
    const uint32_t dwo = (uint32_t)(r * FW + ch * 32) * 4u;

    // Non-trans ldmatrix.x4 B-fragment addressing on [n][k] planes:
    //   r0,r1 = (b0,b1) of n-tile(base), r2,r3 = (b0,b1) of n-tile(base+8)
    const uint32_t btrow = (uint32_t)((lane & 7) + ((lane >> 4) << 3));
    const uint32_t btcol = (uint32_t)(((lane >> 3) & 1) << 2);

    const __half* khb = g_kh + (size_t)b * SEQ * KVDIM + g * HDIM;
    const __half* klb = g_kl + (size_t)b * SEQ * KVDIM + g * HDIM;
    const __half* vhb = g_vth + ((size_t)b * KVDIM + g * HDIM) * SEQ;
    const __half* vlb = g_vtl + ((size_t)b * KVDIM + g * HDIM) * SEQ;

    // prologue: Q (group), K0 (group), V0 (group)
    {
        const __half* qh = g_qh + ((size_t)(b * SEQ + blockIdx.x * 128 + r)) * CDIM
                         + h * HDIM + ch * 64;
        const __half* ql = g_ql + ((size_t)(b * SEQ + blockIdx.x * 128 + r)) * CDIM
                         + h * HDIM + ch * 64;
#pragma unroll
        for (int j = 0; j < 8; j++) {
            cp16(ub + dwo + 16u * j,                      qh + 8 * j);
            cp16(ub + (uint32_t)FPL * 4u + dwo + 16u * j, ql + 8 * j);
        }
        CP_COMMIT();
        const __half* kh = khb + (size_t)r * KVDIM + ch * 64;
        const __half* kl = klb + (size_t)r * KVDIM + ch * 64;
#pragma unroll
        for (int j = 0; j < 8; j++) {
            cp16(ub + 2u * FPL * 4u + dwo + 16u * j, kh + 8 * j);
            cp16(ub + 3u * FPL * 4u + dwo + 16u * j, kl + 8 * j);
        }
        CP_COMMIT();
        const __half* vh = vhb + (size_t)r * SEQ + ch * 64;
        const __half* vl = vlb + (size_t)r * SEQ + ch * 64;
#pragma unroll
        for (int j = 0; j < 8; j++) {
            cp16(ub + 4u * FPL * 4u + dwo + 16u * j, vh + 8 * j);
            cp16(ub + 5u * FPL * 4u + dwo + 16u * j, vl + 8 * j);
        }
        CP_COMMIT();
    }

    float accO[16][4];
#pragma unroll
    for (int nt = 0; nt < 16; nt++)
#pragma unroll
        for (int q = 0; q < 4; q++) accO[nt][q] = 0.0f;
    float m0 = -INFINITY, m1 = -INFINITY, l0s = 0.0f, l1s = 0.0f;

#pragma unroll 1
    for (int kt = 0; kt < SEQ / 128; kt++) {
        // K(kt) ready (V(kt) may still be in flight)
        CP_WAIT1();
        __syncthreads();

        // S = Q.K^T
        float accS[16][4];
#pragma unroll
        for (int nt = 0; nt < 16; nt++)
#pragma unroll
            for (int q = 0; q < 4; q++) accS[nt][q] = 0.0f;

#pragma unroll
        for (int s = 0; s < 8; s++) {
            const int kw = s * 8;
            const uint32_t aoff =
                (uint32_t)((warp * 16 + (lane & 15)) * FW + kw + (lane >> 4) * 4) * 4u;
            uint32_t qh0, qh1, qh2, qh3, ql0, ql1, ql2, ql3;
            ldsm4(ub + aoff,                      qh0, qh1, qh2, qh3);
            ldsm4(ub + (uint32_t)FPL * 4u + aoff, ql0, ql1, ql2, ql3);
            const uint32_t bbase = ub + 2u * FPL * 4u
                                 + (btrow * FW + (uint32_t)kw + btcol) * 4u;
#pragma unroll
            for (int j = 0; j < 8; j++) {
                const uint32_t ba = bbase + (uint32_t)(16 * j * FW) * 4u;
                uint32_t kh0, kh1, kh2, kh3, kl0, kl1, kl2, kl3;
                ldsm4(ba,                      kh0, kh1, kh2, kh3);
                ldsm4(ba + (uint32_t)FPL * 4u, kl0, kl1, kl2, kl3);
                // interleave the two accumulators: dep distance 2
                mma16(accS[2 * j],     qh0, qh1, qh2, qh3, kh0, kh1);
                mma16(accS[2 * j + 1], qh0, qh1, qh2, qh3, kh2, kh3);
                mma16(accS[2 * j],     qh0, qh1, qh2, qh3, kl0, kl1);
                mma16(accS[2 * j + 1], qh0, qh1, qh2, qh3, kl2, kl3);
                mma16(accS[2 * j],     ql0, ql1, ql2, ql3, kh0, kh1);
                mma16(accS[2 * j + 1], ql0, ql1, ql2, ql3, kh2, kh3);
            }
        }
        __syncthreads();   // all warps done reading K planes

        if (kt + 1 < SEQ / 128) {   // prefetch K(kt+1)
            const __half* kh = khb + (size_t)((kt + 1) * 128 + r) * KVDIM + ch * 64;
            const __half* kl = klb + (size_t)((kt + 1) * 128 + r) * KVDIM + ch * 64;
#pragma unroll
            for (int j = 0; j < 8; j++) {
                cp16(ub + 2u * FPL * 4u + dwo + 16u * j, kh + 8 * j);
                cp16(ub + 3u * FPL * 4u + dwo + 16u * j, kl + 8 * j);
            }
            CP_COMMIT();
        }

        // online softmax (rows g and g+8 of this warp's 16)
        float r0 = -INFINITY, r1 = -INFINITY;
#pragma unroll
        for (int nt = 0; nt < 16; nt++) {
            r0 = fmaxf(r0, fmaxf(accS[nt][0], accS[nt][1]));
            r1 = fmaxf(r1, fmaxf(accS[nt][2], accS[nt][3]));
        }
        r0 = fmaxf(r0, __shfl_xor_sync(0xFFFFFFFFu, r0, 1));
        r0 = fmaxf(r0, __shfl_xor_sync(0xFFFFFFFFu, r0, 2));
        r1 = fmaxf(r1, __shfl_xor_sync(0xFFFFFFFFu, r1, 1));
        r1 = fmaxf(r1, __shfl_xor_sync(0xFFFFFFFFu, r1, 2));
        const float mn0 = fmaxf(m0, r0), mn1 = fmaxf(m1, r1);
        const float a0 = __expf(m0 - mn0), a1 = __expf(m1 - mn1);
        m0 = mn0; m1 = mn1;

        float s0 = 0.0f, s1 = 0.0f;
#pragma unroll
        for (int nt = 0; nt < 16; nt++) {
            accS[nt][0] = __expf(accS[nt][0] - mn0);
            accS[nt][1] = __expf(accS[nt][1] - mn0);
            accS[nt][2] = __expf(accS[nt][2] - mn1);
            accS[nt][3] = __expf(accS[nt][3] - mn1);
            s0 += accS[nt][0] + accS[nt][1];
            s1 += accS[nt][2] + accS[nt][3];
        }
        s0 += __shfl_xor_sync(0xFFFFFFFFu, s0, 1);
        s0 += __shfl_xor_sync(0xFFFFFFFFu, s0, 2);
        s1 += __shfl_xor_sync(0xFFFFFFFFu, s1, 1);
        s1 += __shfl_xor_sync(0xFFFFFFFFu, s1, 2);
        l0s = l0s * a0 + s0;
        l1s = l1s * a1 + s1;

#pragma unroll
        for (int nt = 0; nt < 16; nt++) {
            accO[nt][0] *= a0; accO[nt][1] *= a0;
            accO[nt][2] *= a1; accO[nt][3] *= a1;
        }

        // V(kt) ready (K(kt+1) may still be in flight)
        if (kt + 1 < SEQ / 128) CP_WAIT1(); else CP_WAIT0();
        __syncthreads();

        // O += P.V
#pragma unroll
        for (int s = 0; s < 8; s++) {
            uint32_t pa0, pa1, pa2, pa3, pl0, pl1, pl2, pl3;
            split2(accS[2 * s][0],     accS[2 * s][1],     pa0, pl0);
            split2(accS[2 * s][2],     accS[2 * s][3],     pa1, pl1);
            split2(accS[2 * s + 1][0], accS[2 * s + 1][1], pa2, pl2);
            split2(accS[2 * s + 1][2], accS[2 * s + 1][3], pa3, pl3);
            const uint32_t vbase = ub + 4u * FPL * 4u
                                 + (btrow * FW + (uint32_t)(s * 8) + btcol) * 4u;
#pragma unroll
            for (int j = 0; j < 8; j++) {
                const uint32_t va = vbase + (uint32_t)(16 * j * FW) * 4u;
                uint32_t vh0, vh1, vh2, vh3, vl0, vl1, vl2, vl3;
                ldsm4(va,                      vh0, vh1, vh2, vh3);
                ldsm4(va + (uint32_t)FPL * 4u, vl0, vl1, vl2, vl3);
                // interleave the two accumulators: dep distance 2
                mma16(accO[2 * j],     pa0, pa1, pa2, pa3, vh0, vh1);
                mma16(accO[2 * j + 1], pa0, pa1, pa2, pa3, vh2, vh3);
                mma16(accO[2 * j],     pa0, pa1, pa2, pa3, vl0, vl1);
                mma16(accO[2 * j + 1], pa0, pa1, pa2, pa3, vl2, vl3);
                mma16(accO[2 * j],     pl0, pl1, pl2, pl3, vh0, vh1);
                mma16(accO[2 * j + 1], pl0, pl1, pl2, pl3, vh2, vh3);
            }
        }
        __syncthreads();   // all warps done reading V planes

        if (kt + 1 < SEQ / 128) {   // prefetch V(kt+1)
            const __half* vh = vhb + (size_t)r * SEQ + (kt + 1) * 128 + ch * 64;
            const __half* vl = vlb + (size_t)r * SEQ + (kt + 1) * 128 + ch * 64;
#pragma unroll
            for (int j = 0; j < 8; j++) {
                cp16(ub + 4u * FPL * 4u + dwo + 16u * j, vh + 8 * j);
                cp16(ub + 5u * FPL * 4u + dwo + 16u * j, vl + 8 * j);
            }
            CP_COMMIT();
        }
    }

    // epilogue: O /= l, write split fp16 planes (consumed by o-proj)
    const float i0 = 1.0f / l0s, i1 = 1.0f / l1s;
    const int row0 = blockIdx.x * 128 + warp * 16 + gid;
    const size_t ob = ((size_t)(b * SEQ + row0)) * CDIM + h * HDIM;
#pragma unroll
    for (int nt = 0; nt < 16; nt++) {
        const int col = nt * 8 + 2 * tig;
        uint32_t hw, lw;
        split2(accO[nt][0] * i0, accO[nt][1] * i0, hw, lw);
        *reinterpret_cast<uint32_t*>(g_ah + ob + col) = hw;
        *reinterpret_cast<uint32_t*>(g_al + ob + col) = lw;
        split2(accO[nt][2] * i1, accO[nt][3] * i1, hw, lw);
        *reinterpret_cast<uint32_t*>(g_ah + ob + 8 * CDIM + col) = hw;
        *reinterpret_cast<uint32_t*>(g_al + ob + 8 * CDIM + col) = lw;
    }
}

// ---------------------------------------------------------------------------
// Entry point
// ---------------------------------------------------------------------------
extern "C" void kernel_launch(void* const* d_in, const int* in_sizes, int n_in,
                              void* d_out, int out_size) {
    const float* x  = (const float*)d_in[0];
    const float* Wq = (const float*)d_in[1];
    const float* Wk = (const float*)d_in[2];
    const float* Wv = (const float*)d_in[3];
    const float* Wo = (const float*)d_in[4];
    const int*   sp = (const int*)d_in[5];
    float* out = (float*)d_out;

    static int attr_set = 0;
    if (!attr_set) {
        cudaFuncSetAttribute(k_flash, cudaFuncAttributeMaxDynamicSharedMemorySize,
                             SMEM_FLASH);
        cudaFuncSetAttribute(k_qkv, cudaFuncAttributeMaxDynamicSharedMemorySize,
                             SMEM_PROJ);
        cudaFuncSetAttribute(k_oproj, cudaFuncAttributeMaxDynamicSharedMemorySize,
                             SMEM_PROJ);
        attr_set = 1;
    }

    __half *xh, *xl, *wqh, *wql, *wkh, *wkl, *wvh, *wvl, *woh, *wol;
    cudaGetSymbolAddress((void**)&xh,  g_xh);
    cudaGetSymbolAddress((void**)&xl,  g_xl);
    cudaGetSymbolAddress((void**)&wqh, g_wqh);
    cudaGetSymbolAddress((void**)&wql, g_wql);
    cudaGetSymbolAddress((void**)&wkh, g_wkh);
    cudaGetSymbolAddress((void**)&wkl, g_wkl);
    cudaGetSymbolAddress((void**)&wvh, g_wvh);
    cudaGetSymbolAddress((void**)&wvl, g_wvl);
    cudaGetSymbolAddress((void**)&woh, g_woh);
    cudaGetSymbolAddress((void**)&wol, g_wol);

    const int n4x = MROWS * CDIM / 4, n4q = CDIM * CDIM / 4, n4k = KVDIM * CDIM / 4;
    k_split<<<(n4x + 255) / 256, 256>>>((const float4*)x,  (uint2*)xh,  (uint2*)xl,  n4x);
    k_split<<<(n4q + 255) / 256, 256>>>((const float4*)Wq, (uint2*)wqh, (uint2*)wql, n4q);
    k_split<<<(n4k + 255) / 256, 256>>>((const float4*)Wk, (uint2*)wkh, (uint2*)wkl, n4k);
    k_split<<<(n4k + 255) / 256, 256>>>((const float4*)Wv, (uint2*)wvh, (uint2*)wvl, n4k);
    k_split<<<(n4q + 255) / 256, 256>>>((const float4*)Wo, (uint2*)woh, (uint2*)wol, n4q);

    k_qkv<<<dim3(24, MROWS / BM), NTHREADS, SMEM_PROJ>>>();
    k_rope_split<<<MROWS, 256>>>(sp);
    k_vt2<<<dim3(SEQ / 32, KVDIM / 32, BATCH), dim3(32, 8)>>>();
    k_flash<<<dim3(SEQ / 128, BATCH * NHEAD), 256, SMEM_FLASH>>>();
    k_oproj<<<dim3(CDIM / BN, MROWS / BM), NTHREADS, SMEM_PROJ>>>(out);
}

// round 16
// speedup vs baseline: 1.0422x; 1.0422x over previous
#include <cuda_runtime.h>
#include <cuda_fp16.h>
#include <math.h>
#include <stdint.h>

// Problem constants
#define BATCH   2
#define SEQ     2048
#define CDIM    2048
#define NHEAD   16
#define NKV     4
#define HDIM    128
#define MROWS   (BATCH * SEQ)          // 4096
#define KVDIM   (NKV * HDIM)           // 512
#define SCALE   0.08838834764831845f   // 1/sqrt(128)

// Projection GEMM tiling
#define BM 128
#define BN 128
#define BK 32
#define RS 20                          // words per smem row (16 data + 4 pad)
#define PLANE_W (128 * RS)
#define PLANE_B (PLANE_W * 4)          // 10240 B
#define SMEM_PROJ (2 * 4 * PLANE_B)    // 81920 B (double-buffered 4 planes)
#define NTHREADS 256

// Flash kernel smem: 6 planes of [128 rows x 68 words]
#define FW  68
#define FPL (128 * FW)
#define SMEM_FLASH (6 * FPL * 4)       // 208896 B

// ---------------------------------------------------------------------------
// Static device scratch
// ---------------------------------------------------------------------------
__device__ float  g_q[(size_t)MROWS * CDIM];             // fp32 q (pre-rope)
__device__ float  g_k[(size_t)MROWS * KVDIM];
__device__ float  g_v[(size_t)MROWS * KVDIM];
// pre-split fp16 hi/lo planes
__device__ __half g_xh[(size_t)MROWS * CDIM],  g_xl[(size_t)MROWS * CDIM];
__device__ __half g_wqh[(size_t)CDIM * CDIM],  g_wql[(size_t)CDIM * CDIM];
__device__ __half g_wkh[(size_t)KVDIM * CDIM], g_wkl[(size_t)KVDIM * CDIM];
__device__ __half g_wvh[(size_t)KVDIM * CDIM], g_wvl[(size_t)KVDIM * CDIM];
__device__ __half g_woh[(size_t)CDIM * CDIM],  g_wol[(size_t)CDIM * CDIM];
__device__ __half g_qh[(size_t)MROWS * CDIM],  g_ql[(size_t)MROWS * CDIM];
__device__ __half g_kh[(size_t)MROWS * KVDIM], g_kl[(size_t)MROWS * KVDIM];
__device__ __half g_vth[(size_t)BATCH * KVDIM * SEQ], g_vtl[(size_t)BATCH * KVDIM * SEQ];
__device__ __half g_ah[(size_t)MROWS * CDIM],  g_al[(size_t)MROWS * CDIM]; // attn out split

// ---------------------------------------------------------------------------
// Helpers
// ---------------------------------------------------------------------------
__device__ __forceinline__ uint32_t s2u(const void* p) {
    uint32_t a;
    asm("{ .reg .u64 t; cvta.to.shared.u64 t, %1; cvt.u32.u64 %0, t; }" : "=r"(a) : "l"(p));
    return a;
}
__device__ __forceinline__ void split2(float x, float y, uint32_t& hw, uint32_t& lw) {
    __half2 h = __floats2half2_rn(x, y);
    float2 hf = __half22float2(h);
    __half2 l = __floats2half2_rn(x - hf.x, y - hf.y);
    hw = *reinterpret_cast<uint32_t*>(&h);
    lw = *reinterpret_cast<uint32_t*>(&l);
}
__device__ __forceinline__ uint32_t pack2h(float x, float y) {
    __half2 h = __floats2half2_rn(x, y);
    return *reinterpret_cast<uint32_t*>(&h);
}
__device__ __forceinline__ void ldsm4(uint32_t addr, uint32_t& r0, uint32_t& r1,
                                      uint32_t& r2, uint32_t& r3) {
    asm volatile("ldmatrix.sync.aligned.m8n8.x4.shared.b16 {%0,%1,%2,%3}, [%4];"
                 : "=r"(r0), "=r"(r1), "=r"(r2), "=r"(r3) : "r"(addr));
}
__device__ __forceinline__ void mma16(float* d, uint32_t a0, uint32_t a1, uint32_t a2,
                                      uint32_t a3, uint32_t b0, uint32_t b1) {
    asm volatile(
        "mma.sync.aligned.m16n8k16.row.col.f32.f16.f16.f32 "
        "{%0,%1,%2,%3}, {%4,%5,%6,%7}, {%8,%9}, {%0,%1,%2,%3};"
        : "+f"(d[0]), "+f"(d[1]), "+f"(d[2]), "+f"(d[3])
        : "r"(a0), "r"(a1), "r"(a2), "r"(a3), "r"(b0), "r"(b1));
}
__device__ __forceinline__ void cp16(uint32_t dst, const void* src) {
    asm volatile("cp.async.cg.shared.global [%0], [%1], 16;" :: "r"(dst), "l"(src));
}
#define CP_COMMIT() asm volatile("cp.async.commit_group;" ::: "memory")
#define CP_WAIT0()  asm volatile("cp.async.wait_group 0;" ::: "memory")
#define CP_WAIT1()  asm volatile("cp.async.wait_group 1;" ::: "memory")

// ---------------------------------------------------------------------------
// Elementwise fp16 hi/lo split
// ---------------------------------------------------------------------------
__global__ __launch_bounds__(256) void k_split(const float4* __restrict__ src,
                                               uint2* __restrict__ h,
                                               uint2* __restrict__ l, int n4) {
    int i = blockIdx.x * 256 + threadIdx.x;
    if (i >= n4) return;
    float4 v = src[i];
    uint32_t h0, l0, h1, l1;
    split2(v.x, v.y, h0, l0);
    split2(v.z, v.w, h1, l1);
    h[i] = make_uint2(h0, h1);
    l[i] = make_uint2(l0, l1);
}

// ---------------------------------------------------------------------------
// NT GEMM core on pre-split fp16 planes, cp.async double-buffered staging.
// ---------------------------------------------------------------------------
__device__ void gemm_async_nt(const __half* __restrict__ Ah, const __half* __restrict__ Al,
                              int lda,
                              const __half* __restrict__ Bh, const __half* __restrict__ Bl,
                              int ldb,
                              float* __restrict__ C, int ldc,
                              int K, int bxn, int bym)
{
    extern __shared__ uint32_t psm[];
    const uint32_t ub = s2u(psm);

    const int tid  = threadIdx.x;
    const int lane = tid & 31;
    const int warp = tid >> 5;
    const int gid  = lane >> 2;
    const int tig  = lane & 3;
    const int wm   = (warp & 1) * 64;
    const int wn   = (warp >> 1) * 32;

    const int r  = tid >> 1;
    const int hf = tid & 1;
    const __half* pAh = Ah + (size_t)(bym * BM + r) * lda + hf * 16;
    const __half* pAl = Al + (size_t)(bym * BM + r) * lda + hf * 16;
    const __half* pBh = Bh + (size_t)(bxn * BN + r) * ldb + hf * 16;
    const __half* pBl = Bl + (size_t)(bxn * BN + r) * ldb + hf * 16;
    const uint32_t dst0 = ub + (uint32_t)(r * RS + hf * 8) * 4u;

    float acc[4][4][4];
#pragma unroll
    for (int i = 0; i < 4; i++)
#pragma unroll
        for (int j = 0; j < 4; j++)
#pragma unroll
            for (int q = 0; q < 4; q++) acc[i][j][q] = 0.0f;

    const int NCC = K / BK;

    {
        cp16(dst0,                 pAh);
        cp16(dst0 + 16,            pAh + 8);
        cp16(dst0 + PLANE_B,       pAl);
        cp16(dst0 + PLANE_B + 16,  pAl + 8);
        cp16(dst0 + 2 * PLANE_B,      pBh);
        cp16(dst0 + 2 * PLANE_B + 16, pBh + 8);
        cp16(dst0 + 3 * PLANE_B,      pBl);
        cp16(dst0 + 3 * PLANE_B + 16, pBl + 8);
        CP_COMMIT();
    }

    for (int kc = 0; kc < NCC; kc++) {
        if (kc + 1 < NCC) {
            const uint32_t d = dst0 + (uint32_t)(((kc + 1) & 1) * 4 * PLANE_B);
            const int ko = (kc + 1) * BK;
            cp16(d,                 pAh + ko);
            cp16(d + 16,            pAh + ko + 8);
            cp16(d + PLANE_B,       pAl + ko);
            cp16(d + PLANE_B + 16,  pAl + ko + 8);
            cp16(d + 2 * PLANE_B,      pBh + ko);
            cp16(d + 2 * PLANE_B + 16, pBh + ko + 8);
            cp16(d + 3 * PLANE_B,      pBl + ko);
            cp16(d + 3 * PLANE_B + 16, pBl + ko + 8);
            CP_COMMIT();
            CP_WAIT1();
        } else {
            CP_WAIT0();
        }
        __syncthreads();

        const int bufw = (kc & 1) * 4 * PLANE_W;
        const uint32_t bufb = (uint32_t)(kc & 1) * 4u * PLANE_B;
        const uint32_t* sBh = psm + bufw + 2 * PLANE_W;
        const uint32_t* sBl = psm + bufw + 3 * PLANE_W;

#pragma unroll
        for (int ks = 0; ks < 2; ks++) {
            const int kw = ks * 8;
            uint32_t bh[4][2], bl[4][2];
#pragma unroll
            for (int nt = 0; nt < 4; nt++) {
                const int bidx = (wn + nt * 8 + gid) * RS + kw + tig;
                bh[nt][0] = sBh[bidx];
                bh[nt][1] = sBh[bidx + 4];
                bl[nt][0] = sBl[bidx];
                bl[nt][1] = sBl[bidx + 4];
            }
#pragma unroll
            for (int mt = 0; mt < 4; mt++) {
                const int arow = wm + mt * 16 + (lane & 15);
                const uint32_t aoff = bufb + (uint32_t)(arow * RS + kw + (lane >> 4) * 4) * 4u;
                uint32_t ah0, ah1, ah2, ah3, al0, al1, al2, al3;
                ldsm4(ub + aoff,           ah0, ah1, ah2, ah3);
                ldsm4(ub + PLANE_B + aoff, al0, al1, al2, al3);
                // term-major: consecutive MMAs hit different accumulators
#pragma unroll
                for (int nt = 0; nt < 4; nt++)
                    mma16(acc[mt][nt], ah0, ah1, ah2, ah3, bh[nt][0], bh[nt][1]);
#pragma unroll
                for (int nt = 0; nt < 4; nt++)
                    mma16(acc[mt][nt], ah0, ah1, ah2, ah3, bl[nt][0], bl[nt][1]);
#pragma unroll
                for (int nt = 0; nt < 4; nt++)
                    mma16(acc[mt][nt], al0, al1, al2, al3, bh[nt][0], bh[nt][1]);
            }
        }
        __syncthreads();
    }

    float* Cb = C + (size_t)bym * BM * ldc + (size_t)bxn * BN;
#pragma unroll
    for (int mt = 0; mt < 4; mt++) {
        const int row = wm + mt * 16 + gid;
#pragma unroll
        for (int nt = 0; nt < 4; nt++) {
            const int col = wn + nt * 8 + 2 * tig;
            *reinterpret_cast<float2*>(Cb + (size_t)row * ldc + col) =
                make_float2(acc[mt][nt][0], acc[mt][nt][1]);
            *reinterpret_cast<float2*>(Cb + (size_t)(row + 8) * ldc + col) =
                make_float2(acc[mt][nt][2], acc[mt][nt][3]);
        }
    }
}

// Fused Q/K/V projections: grid.x = 24 (16 Q, 4 K, 4 V n-blocks). 2 CTAs/SM.
__global__ __launch_bounds__(NTHREADS, 2) void k_qkv() {
    const int bx = blockIdx.x;
    const __half *Bh, *Bl;
    float* O;
    int ldo, nb;
    if (bx < 16)      { Bh = g_wqh; Bl = g_wql; O = g_q; ldo = CDIM;  nb = bx; }
    else if (bx < 20) { Bh = g_wkh; Bl = g_wkl; O = g_k; ldo = KVDIM; nb = bx - 16; }
    else              { Bh = g_wvh; Bl = g_wvl; O = g_v; ldo = KVDIM; nb = bx - 20; }
    gemm_async_nt(g_xh, g_xl, CDIM, Bh, Bl, CDIM, O, ldo, CDIM, nb, blockIdx.y);
}
__global__ __launch_bounds__(NTHREADS, 2) void k_oproj(float* __restrict__ out) {
    gemm_async_nt(g_ah, g_al, CDIM, g_woh, g_wol, CDIM, out, CDIM, CDIM,
                  blockIdx.x, blockIdx.y);
}

// ---------------------------------------------------------------------------
// RoPE + fp16 pre-split (scaled q, k)
// ---------------------------------------------------------------------------
__global__ void k_rope_split(const int* __restrict__ start_pos) {
    __shared__ float cs[HDIM / 2], sn[HDIM / 2];
    const int bt  = blockIdx.x;
    const int t   = bt & (SEQ - 1);
    const int tid = threadIdx.x;

    if (tid < HDIM / 2) {
        double inv = pow(10000.0, -(double)(2 * tid) / (double)HDIM);
        double ang = (double)(t + start_pos[0]) * inv;
        cs[tid] = (float)cos(ang);
        sn[tid] = (float)sin(ang);
    }
    __syncthreads();

    const float* qrow = g_q + (size_t)bt * CDIM;
    __half* qh = g_qh + (size_t)bt * CDIM;
    __half* ql = g_ql + (size_t)bt * CDIM;
    for (int idx = tid; idx < NHEAD * (HDIM / 2); idx += blockDim.x) {
        int h = idx >> 6, i = idx & 63;
        float x1 = qrow[h * HDIM + i];
        float x2 = qrow[h * HDIM + i + 64];
        float r1 = (x1 * cs[i] - x2 * sn[i]) * SCALE;
        float r2 = (x2 * cs[i] + x1 * sn[i]) * SCALE;
        __half h1 = __float2half_rn(r1);
        __half h2 = __float2half_rn(r2);
        qh[h * HDIM + i]      = h1;
        ql[h * HDIM + i]      = __float2half_rn(r1 - __half2float(h1));
        qh[h * HDIM + i + 64] = h2;
        ql[h * HDIM + i + 64] = __float2half_rn(r2 - __half2float(h2));
    }

    const float* krow = g_k + (size_t)bt * KVDIM;
    __half* kh = g_kh + (size_t)bt * KVDIM;
    __half* kl = g_kl + (size_t)bt * KVDIM;
    for (int idx = tid; idx < NKV * (HDIM / 2); idx += blockDim.x) {
        int h = idx >> 6, i = idx & 63;
        float x1 = krow[h * HDIM + i];
        float x2 = krow[h * HDIM + i + 64];
        float r1 = x1 * cs[i] - x2 * sn[i];
        float r2 = x2 * cs[i] + x1 * sn[i];
        __half h1 = __float2half_rn(r1);
        __half h2 = __float2half_rn(r2);
        kh[h * HDIM + i]      = h1;
        kl[h * HDIM + i]      = __float2half_rn(r1 - __half2float(h1));
        kh[h * HDIM + i + 64] = h2;
        kl[h * HDIM + i + 64] = __float2half_rn(r2 - __half2float(h2));
    }
}

// ---------------------------------------------------------------------------
// V transpose + split
// ---------------------------------------------------------------------------
__global__ void k_vt2() {
    __shared__ float tile[32][33];
    const int b  = blockIdx.z;
    const int t0 = blockIdx.x * 32;
    const int d0 = blockIdx.y * 32;
    const int tx = threadIdx.x, ty = threadIdx.y;
#pragma unroll
    for (int j = 0; j < 4; j++) {
        tile[ty + 8 * j][tx] =
            g_v[((size_t)b * SEQ + t0 + ty + 8 * j) * KVDIM + d0 + tx];
    }
    __syncthreads();
#pragma unroll
    for (int j = 0; j < 4; j++) {
        float v = tile[tx][ty + 8 * j];
        __half hh = __float2half_rn(v);
        size_t o = ((size_t)b * KVDIM + d0 + ty + 8 * j) * SEQ + t0 + tx;
        g_vth[o] = hh;
        g_vtl[o] = __float2half_rn(v - __half2float(hh));
    }
}

// ---------------------------------------------------------------------------
// Fused flash attention: pipelined cp.async staging; non-trans ldmatrix B
// fragments. P uses a 2-term product (Ph*Vh + Ph*Vl): P in [0,1] post-softmax
// with sum 1 -> dropped Pl*Vh term contributes ~2^-11 relative error on O,
// well under the 1e-3 gate. QK stays 3-term (logit errors are pre-exp).
// grid (SEQ/128, BATCH*NHEAD), 256 threads, 1 CTA/SM.
// ---------------------------------------------------------------------------
__global__ __launch_bounds__(256, 1) void k_flash() {
    extern __shared__ uint32_t fsm[];
    const uint32_t ub = s2u(fsm);

    const int tid  = threadIdx.x;
    const int lane = tid & 31;
    const int warp = tid >> 5;
    const int gid  = lane >> 2;
    const int tig  = lane & 3;
    const int z = blockIdx.y, b = z >> 4, h = z & 15, g = h >> 2;

    const int r  = tid >> 1;
    const int ch = tid & 1;
    const uint32_t dwo = (uint32_t)(r * FW + ch * 32) * 4u;

    // Non-trans ldmatrix.x4 B-fragment addressing on [n][k] planes:
    //   r0,r1 = (b0,b1) of n-tile(base), r2,r3 = (b0,b1) of n-tile(base+8)
    const uint32_t btrow = (uint32_t)((lane & 7) + ((lane >> 4) << 3));
    const uint32_t btcol = (uint32_t)(((lane >> 3) & 1) << 2);

    const __half* khb = g_kh + (size_t)b * SEQ * KVDIM + g * HDIM;
    const __half* klb = g_kl + (size_t)b * SEQ * KVDIM + g * HDIM;
    const __half* vhb = g_vth + ((size_t)b * KVDIM + g * HDIM) * SEQ;
    const __half* vlb = g_vtl + ((size_t)b * KVDIM + g * HDIM) * SEQ;

    // prologue: Q (group), K0 (group), V0 (group)
    {
        const __half* qh = g_qh + ((size_t)(b * SEQ + blockIdx.x * 128 + r)) * CDIM
                         + h * HDIM + ch * 64;
        const __half* ql = g_ql + ((size_t)(b * SEQ + blockIdx.x * 128 + r)) * CDIM
                         + h * HDIM + ch * 64;
#pragma unroll
        for (int j = 0; j < 8; j++) {
            cp16(ub + dwo + 16u * j,                      qh + 8 * j);
            cp16(ub + (uint32_t)FPL * 4u + dwo + 16u * j, ql + 8 * j);
        }
        CP_COMMIT();
        const __half* kh = khb + (size_t)r * KVDIM + ch * 64;
        const __half* kl = klb + (size_t)r * KVDIM + ch * 64;
#pragma unroll
        for (int j = 0; j < 8; j++) {
            cp16(ub + 2u * FPL * 4u + dwo + 16u * j, kh + 8 * j);
            cp16(ub + 3u * FPL * 4u + dwo + 16u * j, kl + 8 * j);
        }
        CP_COMMIT();
        const __half* vh = vhb + (size_t)r * SEQ + ch * 64;
        const __half* vl = vlb + (size_t)r * SEQ + ch * 64;
#pragma unroll
        for (int j = 0; j < 8; j++) {
            cp16(ub + 4u * FPL * 4u + dwo + 16u * j, vh + 8 * j);
            cp16(ub + 5u * FPL * 4u + dwo + 16u * j, vl + 8 * j);
        }
        CP_COMMIT();
    }

    float accO[16][4];
#pragma unroll
    for (int nt = 0; nt < 16; nt++)
#pragma unroll
        for (int q = 0; q < 4; q++) accO[nt][q] = 0.0f;
    float m0 = -INFINITY, m1 = -INFINITY, l0s = 0.0f, l1s = 0.0f;

#pragma unroll 1
    for (int kt = 0; kt < SEQ / 128; kt++) {
        // K(kt) ready (V(kt) may still be in flight)
        CP_WAIT1();
        __syncthreads();

        // S = Q.K^T (3-term)
        float accS[16][4];
#pragma unroll
        for (int nt = 0; nt < 16; nt++)
#pragma unroll
            for (int q = 0; q < 4; q++) accS[nt][q] = 0.0f;

#pragma unroll
        for (int s = 0; s < 8; s++) {
            const int kw = s * 8;
            const uint32_t aoff =
                (uint32_t)((warp * 16 + (lane & 15)) * FW + kw + (lane >> 4) * 4) * 4u;
            uint32_t qh0, qh1, qh2, qh3, ql0, ql1, ql2, ql3;
            ldsm4(ub + aoff,                      qh0, qh1, qh2, qh3);
            ldsm4(ub + (uint32_t)FPL * 4u + aoff, ql0, ql1, ql2, ql3);
            const uint32_t bbase = ub + 2u * FPL * 4u
                                 + (btrow * FW + (uint32_t)kw + btcol) * 4u;
#pragma unroll
            for (int j = 0; j < 8; j++) {
                const uint32_t ba = bbase + (uint32_t)(16 * j * FW) * 4u;
                uint32_t kh0, kh1, kh2, kh3, kl0, kl1, kl2, kl3;
                ldsm4(ba,                      kh0, kh1, kh2, kh3);
                ldsm4(ba + (uint32_t)FPL * 4u, kl0, kl1, kl2, kl3);
                mma16(accS[2 * j],     qh0, qh1, qh2, qh3, kh0, kh1);
                mma16(accS[2 * j + 1], qh0, qh1, qh2, qh3, kh2, kh3);
                mma16(accS[2 * j],     qh0, qh1, qh2, qh3, kl0, kl1);
                mma16(accS[2 * j + 1], qh0, qh1, qh2, qh3, kl2, kl3);
                mma16(accS[2 * j],     ql0, ql1, ql2, ql3, kh0, kh1);
                mma16(accS[2 * j + 1], ql0, ql1, ql2, ql3, kh2, kh3);
            }
        }
        __syncthreads();   // all warps done reading K planes

        if (kt + 1 < SEQ / 128) {   // prefetch K(kt+1)
            const __half* kh = khb + (size_t)((kt + 1) * 128 + r) * KVDIM + ch * 64;
            const __half* kl = klb + (size_t)((kt + 1) * 128 + r) * KVDIM + ch * 64;
#pragma unroll
            for (int j = 0; j < 8; j++) {
                cp16(ub + 2u * FPL * 4u + dwo + 16u * j, kh + 8 * j);
                cp16(ub + 3u * FPL * 4u + dwo + 16u * j, kl + 8 * j);
            }
            CP_COMMIT();
        }

        // online softmax (rows g and g+8 of this warp's 16)
        float r0 = -INFINITY, r1 = -INFINITY;
#pragma unroll
        for (int nt = 0; nt < 16; nt++) {
            r0 = fmaxf(r0, fmaxf(accS[nt][0], accS[nt][1]));
            r1 = fmaxf(r1, fmaxf(accS[nt][2], accS[nt][3]));
        }
        r0 = fmaxf(r0, __shfl_xor_sync(0xFFFFFFFFu, r0, 1));
        r0 = fmaxf(r0, __shfl_xor_sync(0xFFFFFFFFu, r0, 2));
        r1 = fmaxf(r1, __shfl_xor_sync(0xFFFFFFFFu, r1, 1));
        r1 = fmaxf(r1, __shfl_xor_sync(0xFFFFFFFFu, r1, 2));
        const float mn0 = fmaxf(m0, r0), mn1 = fmaxf(m1, r1);
        const float a0 = __expf(m0 - mn0), a1 = __expf(m1 - mn1);
        m0 = mn0; m1 = mn1;

        float s0 = 0.0f, s1 = 0.0f;
#pragma unroll
        for (int nt = 0; nt < 16; nt++) {
            accS[nt][0] = __expf(accS[nt][0] - mn0);
            accS[nt][1] = __expf(accS[nt][1] - mn0);
            accS[nt][2] = __expf(accS[nt][2] - mn1);
            accS[nt][3] = __expf(accS[nt][3] - mn1);
            s0 += accS[nt][0] + accS[nt][1];
            s1 += accS[nt][2] + accS[nt][3];
        }
        s0 += __shfl_xor_sync(0xFFFFFFFFu, s0, 1);
        s0 += __shfl_xor_sync(0xFFFFFFFFu, s0, 2);
        s1 += __shfl_xor_sync(0xFFFFFFFFu, s1, 1);
        s1 += __shfl_xor_sync(0xFFFFFFFFu, s1, 2);
        l0s = l0s * a0 + s0;
        l1s = l1s * a1 + s1;

#pragma unroll
        for (int nt = 0; nt < 16; nt++) {
            accO[nt][0] *= a0; accO[nt][1] *= a0;
            accO[nt][2] *= a1; accO[nt][3] *= a1;
        }

        // V(kt) ready (K(kt+1) may still be in flight)
        if (kt + 1 < SEQ / 128) CP_WAIT1(); else CP_WAIT0();
        __syncthreads();

        // O += P.V  (2-term: Ph*Vh + Ph*Vl; Pl dropped — see kernel comment)
#pragma unroll
        for (int s = 0; s < 8; s++) {
            const uint32_t pa0 = pack2h(accS[2 * s][0],     accS[2 * s][1]);
            const uint32_t pa1 = pack2h(accS[2 * s][2],     accS[2 * s][3]);
            const uint32_t pa2 = pack2h(accS[2 * s + 1][0], accS[2 * s + 1][1]);
            const uint32_t pa3 = pack2h(accS[2 * s + 1][2], accS[2 * s + 1][3]);
            const uint32_t vbase = ub + 4u * FPL * 4u
                                 + (btrow * FW + (uint32_t)(s * 8) + btcol) * 4u;
#pragma unroll
            for (int j = 0; j < 8; j++) {
                const uint32_t va = vbase + (uint32_t)(16 * j * FW) * 4u;
                uint32_t vh0, vh1, vh2, vh3, vl0, vl1, vl2, vl3;
                ldsm4(va,                      vh0, vh1, vh2, vh3);
                ldsm4(va + (uint32_t)FPL * 4u, vl0, vl1, vl2, vl3);
                mma16(accO[2 * j],     pa0, pa1, pa2, pa3, vh0, vh1);
                mma16(accO[2 * j + 1], pa0, pa1, pa2, pa3, vh2, vh3);
                mma16(accO[2 * j],     pa0, pa1, pa2, pa3, vl0, vl1);
                mma16(accO[2 * j + 1], pa0, pa1, pa2, pa3, vl2, vl3);
            }
        }
        __syncthreads();   // all warps done reading V planes

        if (kt + 1 < SEQ / 128) {   // prefetch V(kt+1)
            const __half* vh = vhb + (size_t)r * SEQ + (kt + 1) * 128 + ch * 64;
            const __half* vl = vlb + (size_t)r * SEQ + (kt + 1) * 128 + ch * 64;
#pragma unroll
            for (int j = 0; j < 8; j++) {
                cp16(ub + 4u * FPL * 4u + dwo + 16u * j, vh + 8 * j);
                cp16(ub + 5u * FPL * 4u + dwo + 16u * j, vl + 8 * j);
            }
            CP_COMMIT();
        }
    }

    // epilogue: O /= l, write split fp16 planes (consumed by o-proj)
    const float i0 = 1.0f / l0s, i1 = 1.0f / l1s;
    const int row0 = blockIdx.x * 128 + warp * 16 + gid;
    const size_t ob = ((size_t)(b * SEQ + row0)) * CDIM + h * HDIM;
#pragma unroll
    for (int nt = 0; nt < 16; nt++) {
        const int col = nt * 8 + 2 * tig;
        uint32_t hw, lw;
        split2(accO[nt][0] * i0, accO[nt][1] * i0, hw, lw);
        *reinterpret_cast<uint32_t*>(g_ah + ob + col) = hw;
        *reinterpret_cast<uint32_t*>(g_al + ob + col) = lw;
        split2(accO[nt][2] * i1, accO[nt][3] * i1, hw, lw);
        *reinterpret_cast<uint32_t*>(g_ah + ob + 8 * CDIM + col) = hw;
        *reinterpret_cast<uint32_t*>(g_al + ob + 8 * CDIM + col) = lw;
    }
}

// ---------------------------------------------------------------------------
// Entry point
// ---------------------------------------------------------------------------
extern "C" void kernel_launch(void* const* d_in, const int* in_sizes, int n_in,
                              void* d_out, int out_size) {
    const float* x  = (const float*)d_in[0];
    const float* Wq = (const float*)d_in[1];
    const float* Wk = (const float*)d_in[2];
    const float* Wv = (const float*)d_in[3];
    const float* Wo = (const float*)d_in[4];
    const int*   sp = (const int*)d_in[5];
    float* out = (float*)d_out;

    static int attr_set = 0;
    if (!attr_set) {
        cudaFuncSetAttribute(k_flash, cudaFuncAttributeMaxDynamicSharedMemorySize,
                             SMEM_FLASH);
        cudaFuncSetAttribute(k_qkv, cudaFuncAttributeMaxDynamicSharedMemorySize,
                             SMEM_PROJ);
        cudaFuncSetAttribute(k_oproj, cudaFuncAttributeMaxDynamicSharedMemorySize,
                             SMEM_PROJ);
        attr_set = 1;
    }

    __half *xh, *xl, *wqh, *wql, *wkh, *wkl, *wvh, *wvl, *woh, *wol;
    cudaGetSymbolAddress((void**)&xh,  g_xh);
    cudaGetSymbolAddress((void**)&xl,  g_xl);
    cudaGetSymbolAddress((void**)&wqh, g_wqh);
    cudaGetSymbolAddress((void**)&wql, g_wql);
    cudaGetSymbolAddress((void**)&wkh, g_wkh);
    cudaGetSymbolAddress((void**)&wkl, g_wkl);
    cudaGetSymbolAddress((void**)&wvh, g_wvh);
    cudaGetSymbolAddress((void**)&wvl, g_wvl);
    cudaGetSymbolAddress((void**)&woh, g_woh);
    cudaGetSymbolAddress((void**)&wol, g_wol);

    const int n4x = MROWS * CDIM / 4, n4q = CDIM * CDIM / 4, n4k = KVDIM * CDIM / 4;
    k_split<<<(n4x + 255) / 256, 256>>>((const float4*)x,  (uint2*)xh,  (uint2*)xl,  n4x);
    k_split<<<(n4q + 255) / 256, 256>>>((const float4*)Wq, (uint2*)wqh, (uint2*)wql, n4q);
    k_split<<<(n4k + 255) / 256, 256>>>((const float4*)Wk, (uint2*)wkh, (uint2*)wkl, n4k);
    k_split<<<(n4k + 255) / 256, 256>>>((const float4*)Wv, (uint2*)wvh, (uint2*)wvl, n4k);
    k_split<<<(n4q + 255) / 256, 256>>>((const float4*)Wo, (uint2*)woh, (uint2*)wol, n4q);

    k_qkv<<<dim3(24, MROWS / BM), NTHREADS, SMEM_PROJ>>>();
    k_rope_split<<<MROWS, 256>>>(sp);
    k_vt2<<<dim3(SEQ / 32, KVDIM / 32, BATCH), dim3(32, 8)>>>();
    k_flash<<<dim3(SEQ / 128, BATCH * NHEAD), 256, SMEM_FLASH>>>();
    k_oproj<<<dim3(CDIM / BN, MROWS / BM), NTHREADS, SMEM_PROJ>>>(out);
}

// round 17
// speedup vs baseline: 1.1409x; 1.0946x over previous
#include <cuda_runtime.h>
#include <cuda_fp16.h>
#include <math.h>
#include <stdint.h>

// Problem constants
#define BATCH   2
#define SEQ     2048
#define CDIM    2048
#define NHEAD   16
#define NKV     4
#define HDIM    128
#define MROWS   (BATCH * SEQ)          // 4096
#define KVDIM   (NKV * HDIM)           // 512
#define SCALE   0.08838834764831845f   // 1/sqrt(128)

// Projection GEMM tiling
#define BM 128
#define BN 128
#define BK 32
#define RS 20                          // words per smem row (16 data + 4 pad)
#define PLANE_W (128 * RS)
#define PLANE_B (PLANE_W * 4)          // 10240 B
#define SMEM_PROJ (2 * 4 * PLANE_B)    // 81920 B (double-buffered 4 planes)
#define NTHREADS 256

// Flash kernel smem: 6 planes of [128 rows x 68 words] (plane 3 unused now)
#define FW  68
#define FPL (128 * FW)
#define SMEM_FLASH (6 * FPL * 4)       // 208896 B

// ---------------------------------------------------------------------------
// Static device scratch
// ---------------------------------------------------------------------------
__device__ float  g_q[(size_t)MROWS * CDIM];             // fp32 q (pre-rope)
__device__ float  g_k[(size_t)MROWS * KVDIM];
__device__ float  g_v[(size_t)MROWS * KVDIM];
// pre-split fp16 hi/lo planes
__device__ __half g_xh[(size_t)MROWS * CDIM],  g_xl[(size_t)MROWS * CDIM];
__device__ __half g_wqh[(size_t)CDIM * CDIM],  g_wql[(size_t)CDIM * CDIM];
__device__ __half g_wkh[(size_t)KVDIM * CDIM], g_wkl[(size_t)KVDIM * CDIM];
__device__ __half g_wvh[(size_t)KVDIM * CDIM], g_wvl[(size_t)KVDIM * CDIM];
__device__ __half g_woh[(size_t)CDIM * CDIM],  g_wol[(size_t)CDIM * CDIM];
__device__ __half g_qh[(size_t)MROWS * CDIM],  g_ql[(size_t)MROWS * CDIM];
__device__ __half g_kh[(size_t)MROWS * KVDIM];           // K hi only (2-term QK)
__device__ __half g_vth[(size_t)BATCH * KVDIM * SEQ], g_vtl[(size_t)BATCH * KVDIM * SEQ];
__device__ __half g_ah[(size_t)MROWS * CDIM],  g_al[(size_t)MROWS * CDIM]; // attn out split

// ---------------------------------------------------------------------------
// Helpers
// ---------------------------------------------------------------------------
__device__ __forceinline__ uint32_t s2u(const void* p) {
    uint32_t a;
    asm("{ .reg .u64 t; cvta.to.shared.u64 t, %1; cvt.u32.u64 %0, t; }" : "=r"(a) : "l"(p));
    return a;
}
__device__ __forceinline__ void split2(float x, float y, uint32_t& hw, uint32_t& lw) {
    __half2 h = __floats2half2_rn(x, y);
    float2 hf = __half22float2(h);
    __half2 l = __floats2half2_rn(x - hf.x, y - hf.y);
    hw = *reinterpret_cast<uint32_t*>(&h);
    lw = *reinterpret_cast<uint32_t*>(&l);
}
__device__ __forceinline__ uint32_t pack2h(float x, float y) {
    __half2 h = __floats2half2_rn(x, y);
    return *reinterpret_cast<uint32_t*>(&h);
}
__device__ __forceinline__ void ldsm4(uint32_t addr, uint32_t& r0, uint32_t& r1,
                                      uint32_t& r2, uint32_t& r3) {
    asm volatile("ldmatrix.sync.aligned.m8n8.x4.shared.b16 {%0,%1,%2,%3}, [%4];"
                 : "=r"(r0), "=r"(r1), "=r"(r2), "=r"(r3) : "r"(addr));
}
__device__ __forceinline__ void mma16(float* d, uint32_t a0, uint32_t a1, uint32_t a2,
                                      uint32_t a3, uint32_t b0, uint32_t b1) {
    asm volatile(
        "mma.sync.aligned.m16n8k16.row.col.f32.f16.f16.f32 "
        "{%0,%1,%2,%3}, {%4,%5,%6,%7}, {%8,%9}, {%0,%1,%2,%3};"
        : "+f"(d[0]), "+f"(d[1]), "+f"(d[2]), "+f"(d[3])
        : "r"(a0), "r"(a1), "r"(a2), "r"(a3), "r"(b0), "r"(b1));
}
__device__ __forceinline__ void cp16(uint32_t dst, const void* src) {
    asm volatile("cp.async.cg.shared.global [%0], [%1], 16;" :: "r"(dst), "l"(src));
}
#define CP_COMMIT() asm volatile("cp.async.commit_group;" ::: "memory")
#define CP_WAIT0()  asm volatile("cp.async.wait_group 0;" ::: "memory")
#define CP_WAIT1()  asm volatile("cp.async.wait_group 1;" ::: "memory")

// ---------------------------------------------------------------------------
// Elementwise fp16 hi/lo split
// ---------------------------------------------------------------------------
__global__ __launch_bounds__(256) void k_split(const float4* __restrict__ src,
                                               uint2* __restrict__ h,
                                               uint2* __restrict__ l, int n4) {
    int i = blockIdx.x * 256 + threadIdx.x;
    if (i >= n4) return;
    float4 v = src[i];
    uint32_t h0, l0, h1, l1;
    split2(v.x, v.y, h0, l0);
    split2(v.z, v.w, h1, l1);
    h[i] = make_uint2(h0, h1);
    l[i] = make_uint2(l0, l1);
}

// ---------------------------------------------------------------------------
// NT GEMM core on pre-split fp16 planes, cp.async double-buffered staging.
// ---------------------------------------------------------------------------
__device__ void gemm_async_nt(const __half* __restrict__ Ah, const __half* __restrict__ Al,
                              int lda,
                              const __half* __restrict__ Bh, const __half* __restrict__ Bl,
                              int ldb,
                              float* __restrict__ C, int ldc,
                              int K, int bxn, int bym)
{
    extern __shared__ uint32_t psm[];
    const uint32_t ub = s2u(psm);

    const int tid  = threadIdx.x;
    const int lane = tid & 31;
    const int warp = tid >> 5;
    const int gid  = lane >> 2;
    const int tig  = lane & 3;
    const int wm   = (warp & 1) * 64;
    const int wn   = (warp >> 1) * 32;

    const int r  = tid >> 1;
    const int hf = tid & 1;
    const __half* pAh = Ah + (size_t)(bym * BM + r) * lda + hf * 16;
    const __half* pAl = Al + (size_t)(bym * BM + r) * lda + hf * 16;
    const __half* pBh = Bh + (size_t)(bxn * BN + r) * ldb + hf * 16;
    const __half* pBl = Bl + (size_t)(bxn * BN + r) * ldb + hf * 16;
    const uint32_t dst0 = ub + (uint32_t)(r * RS + hf * 8) * 4u;

    float acc[4][4][4];
#pragma unroll
    for (int i = 0; i < 4; i++)
#pragma unroll
        for (int j = 0; j < 4; j++)
#pragma unroll
            for (int q = 0; q < 4; q++) acc[i][j][q] = 0.0f;

    const int NCC = K / BK;

    {
        cp16(dst0,                 pAh);
        cp16(dst0 + 16,            pAh + 8);
        cp16(dst0 + PLANE_B,       pAl);
        cp16(dst0 + PLANE_B + 16,  pAl + 8);
        cp16(dst0 + 2 * PLANE_B,      pBh);
        cp16(dst0 + 2 * PLANE_B + 16, pBh + 8);
        cp16(dst0 + 3 * PLANE_B,      pBl);
        cp16(dst0 + 3 * PLANE_B + 16, pBl + 8);
        CP_COMMIT();
    }

    for (int kc = 0; kc < NCC; kc++) {
        if (kc + 1 < NCC) {
            const uint32_t d = dst0 + (uint32_t)(((kc + 1) & 1) * 4 * PLANE_B);
            const int ko = (kc + 1) * BK;
            cp16(d,                 pAh + ko);
            cp16(d + 16,            pAh + ko + 8);
            cp16(d + PLANE_B,       pAl + ko);
            cp16(d + PLANE_B + 16,  pAl + ko + 8);
            cp16(d + 2 * PLANE_B,      pBh + ko);
            cp16(d + 2 * PLANE_B + 16, pBh + ko + 8);
            cp16(d + 3 * PLANE_B,      pBl + ko);
            cp16(d + 3 * PLANE_B + 16, pBl + ko + 8);
            CP_COMMIT();
            CP_WAIT1();
        } else {
            CP_WAIT0();
        }
        __syncthreads();

        const int bufw = (kc & 1) * 4 * PLANE_W;
        const uint32_t bufb = (uint32_t)(kc & 1) * 4u * PLANE_B;
        const uint32_t* sBh = psm + bufw + 2 * PLANE_W;
        const uint32_t* sBl = psm + bufw + 3 * PLANE_W;

#pragma unroll
        for (int ks = 0; ks < 2; ks++) {
            const int kw = ks * 8;
            uint32_t bh[4][2], bl[4][2];
#pragma unroll
            for (int nt = 0; nt < 4; nt++) {
                const int bidx = (wn + nt * 8 + gid) * RS + kw + tig;
                bh[nt][0] = sBh[bidx];
                bh[nt][1] = sBh[bidx + 4];
                bl[nt][0] = sBl[bidx];
                bl[nt][1] = sBl[bidx + 4];
            }
#pragma unroll
            for (int mt = 0; mt < 4; mt++) {
                const int arow = wm + mt * 16 + (lane & 15);
                const uint32_t aoff = bufb + (uint32_t)(arow * RS + kw + (lane >> 4) * 4) * 4u;
                uint32_t ah0, ah1, ah2, ah3, al0, al1, al2, al3;
                ldsm4(ub + aoff,           ah0, ah1, ah2, ah3);
                ldsm4(ub + PLANE_B + aoff, al0, al1, al2, al3);
                // term-major: consecutive MMAs hit different accumulators
#pragma unroll
                for (int nt = 0; nt < 4; nt++)
                    mma16(acc[mt][nt], ah0, ah1, ah2, ah3, bh[nt][0], bh[nt][1]);
#pragma unroll
                for (int nt = 0; nt < 4; nt++)
                    mma16(acc[mt][nt], ah0, ah1, ah2, ah3, bl[nt][0], bl[nt][1]);
#pragma unroll
                for (int nt = 0; nt < 4; nt++)
                    mma16(acc[mt][nt], al0, al1, al2, al3, bh[nt][0], bh[nt][1]);
            }
        }
        __syncthreads();
    }

    float* Cb = C + (size_t)bym * BM * ldc + (size_t)bxn * BN;
#pragma unroll
    for (int mt = 0; mt < 4; mt++) {
        const int row = wm + mt * 16 + gid;
#pragma unroll
        for (int nt = 0; nt < 4; nt++) {
            const int col = wn + nt * 8 + 2 * tig;
            *reinterpret_cast<float2*>(Cb + (size_t)row * ldc + col) =
                make_float2(acc[mt][nt][0], acc[mt][nt][1]);
            *reinterpret_cast<float2*>(Cb + (size_t)(row + 8) * ldc + col) =
                make_float2(acc[mt][nt][2], acc[mt][nt][3]);
        }
    }
}

// Fused Q/K/V projections: grid.x = 24 (16 Q, 4 K, 4 V n-blocks). 2 CTAs/SM.
__global__ __launch_bounds__(NTHREADS, 2) void k_qkv() {
    const int bx = blockIdx.x;
    const __half *Bh, *Bl;
    float* O;
    int ldo, nb;
    if (bx < 16)      { Bh = g_wqh; Bl = g_wql; O = g_q; ldo = CDIM;  nb = bx; }
    else if (bx < 20) { Bh = g_wkh; Bl = g_wkl; O = g_k; ldo = KVDIM; nb = bx - 16; }
    else              { Bh = g_wvh; Bl = g_wvl; O = g_v; ldo = KVDIM; nb = bx - 20; }
    gemm_async_nt(g_xh, g_xl, CDIM, Bh, Bl, CDIM, O, ldo, CDIM, nb, blockIdx.y);
}
__global__ __launch_bounds__(NTHREADS, 2) void k_oproj(float* __restrict__ out) {
    gemm_async_nt(g_ah, g_al, CDIM, g_woh, g_wol, CDIM, out, CDIM, CDIM,
                  blockIdx.x, blockIdx.y);
}

// ---------------------------------------------------------------------------
// RoPE + fp16 pre-split (scaled split q; K hi only — 2-term QK drops Kl)
// ---------------------------------------------------------------------------
__global__ void k_rope_split(const int* __restrict__ start_pos) {
    __shared__ float cs[HDIM / 2], sn[HDIM / 2];
    const int bt  = blockIdx.x;
    const int t   = bt & (SEQ - 1);
    const int tid = threadIdx.x;

    if (tid < HDIM / 2) {
        double inv = pow(10000.0, -(double)(2 * tid) / (double)HDIM);
        double ang = (double)(t + start_pos[0]) * inv;
        cs[tid] = (float)cos(ang);
        sn[tid] = (float)sin(ang);
    }
    __syncthreads();

    const float* qrow = g_q + (size_t)bt * CDIM;
    __half* qh = g_qh + (size_t)bt * CDIM;
    __half* ql = g_ql + (size_t)bt * CDIM;
    for (int idx = tid; idx < NHEAD * (HDIM / 2); idx += blockDim.x) {
        int h = idx >> 6, i = idx & 63;
        float x1 = qrow[h * HDIM + i];
        float x2 = qrow[h * HDIM + i + 64];
        float r1 = (x1 * cs[i] - x2 * sn[i]) * SCALE;
        float r2 = (x2 * cs[i] + x1 * sn[i]) * SCALE;
        __half h1 = __float2half_rn(r1);
        __half h2 = __float2half_rn(r2);
        qh[h * HDIM + i]      = h1;
        ql[h * HDIM + i]      = __float2half_rn(r1 - __half2float(h1));
        qh[h * HDIM + i + 64] = h2;
        ql[h * HDIM + i + 64] = __float2half_rn(r2 - __half2float(h2));
    }

    const float* krow = g_k + (size_t)bt * KVDIM;
    __half* kh = g_kh + (size_t)bt * KVDIM;
    for (int idx = tid; idx < NKV * (HDIM / 2); idx += blockDim.x) {
        int h = idx >> 6, i = idx & 63;
        float x1 = krow[h * HDIM + i];
        float x2 = krow[h * HDIM + i + 64];
        kh[h * HDIM + i]      = __float2half_rn(x1 * cs[i] - x2 * sn[i]);
        kh[h * HDIM + i + 64] = __float2half_rn(x2 * cs[i] + x1 * sn[i]);
    }
}

// ---------------------------------------------------------------------------
// V transpose + split
// ---------------------------------------------------------------------------
__global__ void k_vt2() {
    __shared__ float tile[32][33];
    const int b  = blockIdx.z;
    const int t0 = blockIdx.x * 32;
    const int d0 = blockIdx.y * 32;
    const int tx = threadIdx.x, ty = threadIdx.y;
#pragma unroll
    for (int j = 0; j < 4; j++) {
        tile[ty + 8 * j][tx] =
            g_v[((size_t)b * SEQ + t0 + ty + 8 * j) * KVDIM + d0 + tx];
    }
    __syncthreads();
#pragma unroll
    for (int j = 0; j < 4; j++) {
        float v = tile[tx][ty + 8 * j];
        __half hh = __float2half_rn(v);
        size_t o = ((size_t)b * KVDIM + d0 + ty + 8 * j) * SEQ + t0 + tx;
        g_vth[o] = hh;
        g_vtl[o] = __float2half_rn(v - __half2float(hh));
    }
}

// ---------------------------------------------------------------------------
// Fused flash attention. 2-term QK (Qh*Kh + Ql*Kh; Kl dropped — logit noise
// ~2.4e-4, pre-calibrated by round-16's Pl drop) and 2-term PV
// (Ph*Vh + Ph*Vl). Kl plane is dead: no staging, no LDSM.
// grid (SEQ/128, BATCH*NHEAD), 256 threads, 1 CTA/SM.
// ---------------------------------------------------------------------------
__global__ __launch_bounds__(256, 1) void k_flash() {
    extern __shared__ uint32_t fsm[];
    const uint32_t ub = s2u(fsm);

    const int tid  = threadIdx.x;
    const int lane = tid & 31;
    const int warp = tid >> 5;
    const int gid  = lane >> 2;
    const int tig  = lane & 3;
    const int z = blockIdx.y, b = z >> 4, h = z & 15, g = h >> 2;

    const int r  = tid >> 1;
    const int ch = tid & 1;
    const uint32_t dwo = (uint32_t)(r * FW + ch * 32) * 4u;

    // Non-trans ldmatrix.x4 B-fragment addressing on [n][k] planes:
    //   r0,r1 = (b0,b1) of n-tile(base), r2,r3 = (b0,b1) of n-tile(base+8)
    const uint32_t btrow = (uint32_t)((lane & 7) + ((lane >> 4) << 3));
    const uint32_t btcol = (uint32_t)(((lane >> 3) & 1) << 2);

    const __half* khb = g_kh + (size_t)b * SEQ * KVDIM + g * HDIM;
    const __half* vhb = g_vth + ((size_t)b * KVDIM + g * HDIM) * SEQ;
    const __half* vlb = g_vtl + ((size_t)b * KVDIM + g * HDIM) * SEQ;

    // prologue: Q (group), K0 (group), V0 (group)
    {
        const __half* qh = g_qh + ((size_t)(b * SEQ + blockIdx.x * 128 + r)) * CDIM
                         + h * HDIM + ch * 64;
        const __half* ql = g_ql + ((size_t)(b * SEQ + blockIdx.x * 128 + r)) * CDIM
                         + h * HDIM + ch * 64;
#pragma unroll
        for (int j = 0; j < 8; j++) {
            cp16(ub + dwo + 16u * j,                      qh + 8 * j);
            cp16(ub + (uint32_t)FPL * 4u + dwo + 16u * j, ql + 8 * j);
        }
        CP_COMMIT();
        const __half* kh = khb + (size_t)r * KVDIM + ch * 64;
#pragma unroll
        for (int j = 0; j < 8; j++)
            cp16(ub + 2u * FPL * 4u + dwo + 16u * j, kh + 8 * j);
        CP_COMMIT();
        const __half* vh = vhb + (size_t)r * SEQ + ch * 64;
        const __half* vl = vlb + (size_t)r * SEQ + ch * 64;
#pragma unroll
        for (int j = 0; j < 8; j++) {
            cp16(ub + 4u * FPL * 4u + dwo + 16u * j, vh + 8 * j);
            cp16(ub + 5u * FPL * 4u + dwo + 16u * j, vl + 8 * j);
        }
        CP_COMMIT();
    }

    float accO[16][4];
#pragma unroll
    for (int nt = 0; nt < 16; nt++)
#pragma unroll
        for (int q = 0; q < 4; q++) accO[nt][q] = 0.0f;
    float m0 = -INFINITY, m1 = -INFINITY, l0s = 0.0f, l1s = 0.0f;

#pragma unroll 1
    for (int kt = 0; kt < SEQ / 128; kt++) {
        // K(kt) ready (V(kt) may still be in flight)
        CP_WAIT1();
        __syncthreads();

        // S = Q.K^T (2-term: Qh*Kh + Ql*Kh)
        float accS[16][4];
#pragma unroll
        for (int nt = 0; nt < 16; nt++)
#pragma unroll
            for (int q = 0; q < 4; q++) accS[nt][q] = 0.0f;

#pragma unroll
        for (int s = 0; s < 8; s++) {
            const int kw = s * 8;
            const uint32_t aoff =
                (uint32_t)((warp * 16 + (lane & 15)) * FW + kw + (lane >> 4) * 4) * 4u;
            uint32_t qh0, qh1, qh2, qh3, ql0, ql1, ql2, ql3;
            ldsm4(ub + aoff,                      qh0, qh1, qh2, qh3);
            ldsm4(ub + (uint32_t)FPL * 4u + aoff, ql0, ql1, ql2, ql3);
            const uint32_t bbase = ub + 2u * FPL * 4u
                                 + (btrow * FW + (uint32_t)kw + btcol) * 4u;
#pragma unroll
            for (int j = 0; j < 8; j++) {
                const uint32_t ba = bbase + (uint32_t)(16 * j * FW) * 4u;
                uint32_t kh0, kh1, kh2, kh3;
                ldsm4(ba, kh0, kh1, kh2, kh3);
                mma16(accS[2 * j],     qh0, qh1, qh2, qh3, kh0, kh1);
                mma16(accS[2 * j + 1], qh0, qh1, qh2, qh3, kh2, kh3);
                mma16(accS[2 * j],     ql0, ql1, ql2, ql3, kh0, kh1);
                mma16(accS[2 * j + 1], ql0, ql1, ql2, ql3, kh2, kh3);
            }
        }
        __syncthreads();   // all warps done reading K plane

        if (kt + 1 < SEQ / 128) {   // prefetch K(kt+1)
            const __half* kh = khb + (size_t)((kt + 1) * 128 + r) * KVDIM + ch * 64;
#pragma unroll
            for (int j = 0; j < 8; j++)
                cp16(ub + 2u * FPL * 4u + dwo + 16u * j, kh + 8 * j);
            CP_COMMIT();
        }

        // online softmax (rows g and g+8 of this warp's 16)
        float r0 = -INFINITY, r1 = -INFINITY;
#pragma unroll
        for (int nt = 0; nt < 16; nt++) {
            r0 = fmaxf(r0, fmaxf(accS[nt][0], accS[nt][1]));
            r1 = fmaxf(r1, fmaxf(accS[nt][2], accS[nt][3]));
        }
        r0 = fmaxf(r0, __shfl_xor_sync(0xFFFFFFFFu, r0, 1));
        r0 = fmaxf(r0, __shfl_xor_sync(0xFFFFFFFFu, r0, 2));
        r1 = fmaxf(r1, __shfl_xor_sync(0xFFFFFFFFu, r1, 1));
        r1 = fmaxf(r1, __shfl_xor_sync(0xFFFFFFFFu, r1, 2));
        const float mn0 = fmaxf(m0, r0), mn1 = fmaxf(m1, r1);
        const float a0 = __expf(m0 - mn0), a1 = __expf(m1 - mn1);
        m0 = mn0; m1 = mn1;

        float s0 = 0.0f, s1 = 0.0f;
#pragma unroll
        for (int nt = 0; nt < 16; nt++) {
            accS[nt][0] = __expf(accS[nt][0] - mn0);
            accS[nt][1] = __expf(accS[nt][1] - mn0);
            accS[nt][2] = __expf(accS[nt][2] - mn1);
            accS[nt][3] = __expf(accS[nt][3] - mn1);
            s0 += accS[nt][0] + accS[nt][1];
            s1 += accS[nt][2] + accS[nt][3];
        }
        s0 += __shfl_xor_sync(0xFFFFFFFFu, s0, 1);
        s0 += __shfl_xor_sync(0xFFFFFFFFu, s0, 2);
        s1 += __shfl_xor_sync(0xFFFFFFFFu, s1, 1);
        s1 += __shfl_xor_sync(0xFFFFFFFFu, s1, 2);
        l0s = l0s * a0 + s0;
        l1s = l1s * a1 + s1;

#pragma unroll
        for (int nt = 0; nt < 16; nt++) {
            accO[nt][0] *= a0; accO[nt][1] *= a0;
            accO[nt][2] *= a1; accO[nt][3] *= a1;
        }

        // V(kt) ready (K(kt+1) may still be in flight)
        if (kt + 1 < SEQ / 128) CP_WAIT1(); else CP_WAIT0();
        __syncthreads();

        // O += P.V  (2-term: Ph*Vh + Ph*Vl)
#pragma unroll
        for (int s = 0; s < 8; s++) {
            const uint32_t pa0 = pack2h(accS[2 * s][0],     accS[2 * s][1]);
            const uint32_t pa1 = pack2h(accS[2 * s][2],     accS[2 * s][3]);
            const uint32_t pa2 = pack2h(accS[2 * s + 1][0], accS[2 * s + 1][1]);
            const uint32_t pa3 = pack2h(accS[2 * s + 1][2], accS[2 * s + 1][3]);
            const uint32_t vbase = ub + 4u * FPL * 4u
                                 + (btrow * FW + (uint32_t)(s * 8) + btcol) * 4u;
#pragma unroll
            for (int j = 0; j < 8; j++) {
                const uint32_t va = vbase + (uint32_t)(16 * j * FW) * 4u;
                uint32_t vh0, vh1, vh2, vh3, vl0, vl1, vl2, vl3;
                ldsm4(va,                      vh0, vh1, vh2, vh3);
                ldsm4(va + (uint32_t)FPL * 4u, vl0, vl1, vl2, vl3);
                mma16(accO[2 * j],     pa0, pa1, pa2, pa3, vh0, vh1);
                mma16(accO[2 * j + 1], pa0, pa1, pa2, pa3, vh2, vh3);
                mma16(accO[2 * j],     pa0, pa1, pa2, pa3, vl0, vl1);
                mma16(accO[2 * j + 1], pa0, pa1, pa2, pa3, vl2, vl3);
            }
        }
        __syncthreads();   // all warps done reading V planes

        if (kt + 1 < SEQ / 128) {   // prefetch V(kt+1)
            const __half* vh = vhb + (size_t)r * SEQ + (kt + 1) * 128 + ch * 64;
            const __half* vl = vlb + (size_t)r * SEQ + (kt + 1) * 128 + ch * 64;
#pragma unroll
            for (int j = 0; j < 8; j++) {
                cp16(ub + 4u * FPL * 4u + dwo + 16u * j, vh + 8 * j);
                cp16(ub + 5u * FPL * 4u + dwo + 16u * j, vl + 8 * j);
            }
            CP_COMMIT();
        }
    }

    // epilogue: O /= l, write split fp16 planes (consumed by o-proj)
    const float i0 = 1.0f / l0s, i1 = 1.0f / l1s;
    const int row0 = blockIdx.x * 128 + warp * 16 + gid;
    const size_t ob = ((size_t)(b * SEQ + row0)) * CDIM + h * HDIM;
#pragma unroll
    for (int nt = 0; nt < 16; nt++) {
        const int col = nt * 8 + 2 * tig;
        uint32_t hw, lw;
        split2(accO[nt][0] * i0, accO[nt][1] * i0, hw, lw);
        *reinterpret_cast<uint32_t*>(g_ah + ob + col) = hw;
        *reinterpret_cast<uint32_t*>(g_al + ob + col) = lw;
        split2(accO[nt][2] * i1, accO[nt][3] * i1, hw, lw);
        *reinterpret_cast<uint32_t*>(g_ah + ob + 8 * CDIM + col) = hw;
        *reinterpret_cast<uint32_t*>(g_al + ob + 8 * CDIM + col) = lw;
    }
}

// ---------------------------------------------------------------------------
// Entry point
// ---------------------------------------------------------------------------
extern "C" void kernel_launch(void* const* d_in, const int* in_sizes, int n_in,
                              void* d_out, int out_size) {
    const float* x  = (const float*)d_in[0];
    const float* Wq = (const float*)d_in[1];
    const float* Wk = (const float*)d_in[2];
    const float* Wv = (const float*)d_in[3];
    const float* Wo = (const float*)d_in[4];
    const int*   sp = (const int*)d_in[5];
    float* out = (float*)d_out;

    static int attr_set = 0;
    if (!attr_set) {
        cudaFuncSetAttribute(k_flash, cudaFuncAttributeMaxDynamicSharedMemorySize,
                             SMEM_FLASH);
        cudaFuncSetAttribute(k_qkv, cudaFuncAttributeMaxDynamicSharedMemorySize,
                             SMEM_PROJ);
        cudaFuncSetAttribute(k_oproj, cudaFuncAttributeMaxDynamicSharedMemorySize,
                             SMEM_PROJ);
        attr_set = 1;
    }

    __half *xh, *xl, *wqh, *wql, *wkh, *wkl, *wvh, *wvl, *woh, *wol;
    cudaGetSymbolAddress((void**)&xh,  g_xh);
    cudaGetSymbolAddress((void**)&xl,  g_xl);
    cudaGetSymbolAddress((void**)&wqh, g_wqh);
    cudaGetSymbolAddress((void**)&wql, g_wql);
    cudaGetSymbolAddress((void**)&wkh, g_wkh);
    cudaGetSymbolAddress((void**)&wkl, g_wkl);
    cudaGetSymbolAddress((void**)&wvh, g_wvh);
    cudaGetSymbolAddress((void**)&wvl, g_wvl);
    cudaGetSymbolAddress((void**)&woh, g_woh);
    cudaGetSymbolAddress((void**)&wol, g_wol);

    const int n4x = MROWS * CDIM / 4, n4q = CDIM * CDIM / 4, n4k = KVDIM * CDIM / 4;
    k_split<<<(n4x + 255) / 256, 256>>>((const float4*)x,  (uint2*)xh,  (uint2*)xl,  n4x);
    k_split<<<(n4q + 255) / 256, 256>>>((const float4*)Wq, (uint2*)wqh, (uint2*)wql, n4q);
    k_split<<<(n4k + 255) / 256, 256>>>((const float4*)Wk, (uint2*)wkh, (uint2*)wkl, n4k);
    k_split<<<(n4k + 255) / 256, 256>>>((const float4*)Wv, (uint2*)wvh, (uint2*)wvl, n4k);
    k_split<<<(n4q + 255) / 256, 256>>>((const float4*)Wo, (uint2*)woh, (uint2*)wol, n4q);

    k_qkv<<<dim3(24, MROWS / BM), NTHREADS, SMEM_PROJ>>>();
    k_rope_split<<<MROWS, 256>>>(sp);
    k_vt2<<<dim3(SEQ / 32, KVDIM / 32, BATCH), dim3(32, 8)>>>();
    k_flash<<<dim3(SEQ / 128, BATCH * NHEAD), 256, SMEM_FLASH>>>();
    k_oproj<<<dim3(CDIM / BN, MROWS / BM), NTHREADS, SMEM_PROJ>>>(out);
}